// round 15
// baseline (speedup 1.0000x reference)
#include <cuda_runtime.h>
#include <cuda_fp16.h>
#include <stdint.h>
#include <math.h>

#define B        128
#define T_ENC    1024
#define KVS      128
#define EMBED    256
#define VOCAB    30
#define MAX_LEN  250
#define GATES    512     // 4*KVS
#define XDIM     384     // EMBED+KVS
#define JROWS    (2*KVS) // 256 rows of recurrent weight matrix [j][g]
#define NT       512     // threads per CTA (128 regs/thread budget)

// -------- persistent device scratch (no allocs allowed) --------
__device__ float  g_keyT[(size_t)B * KVS * T_ENC];     // [b][k][te] fp32 (b==0: exact attn)
__device__ __half g_keyH[(size_t)B * KVS * T_ENC];     // [b][k][te] fp16 (all other b)
__device__ __half g_valH[(size_t)B * T_ENC * KVS];     // [b][te][k] fp16
__device__ float  g_table[(VOCAB + 1) * GATES];        // [v][g], row VOCAB = bias-only
__device__ __half g_WrH[JROWS * GATES];                // [j][g] fp16; j<128: ctx w., j>=128: h w.

// -------- shared memory layout (floats) --------
#define TABLE_F  ((VOCAB + 1) * GATES)   // 15872
#define EMB_F    (VOCAB * EMBED)         // 7680
#define SMEM_F   (TABLE_F + EMB_F + 256 + 128 + 1024 + 2048 + 72 + 32)
#define SMEM_BYTES (SMEM_F * 4)          // ~108 KB

__device__ __forceinline__ float sigm(float x) { return 1.0f / (1.0f + expf(-x)); }

// -------- preprocessing kernels --------
__global__ void transpose_key(const float* __restrict__ key) {
    __shared__ float tile[32][33];
    int b   = blockIdx.z;
    int te0 = blockIdx.x * 32;
    int k0  = blockIdx.y * 32;
    int tx = threadIdx.x, ty = threadIdx.y;       // (32, 8)
    #pragma unroll
    for (int i = ty; i < 32; i += 8)
        tile[i][tx] = key[((size_t)b * T_ENC + te0 + i) * KVS + k0 + tx];
    __syncthreads();
    #pragma unroll
    for (int i = ty; i < 32; i += 8) {
        const float v = tile[tx][i];
        const size_t o = ((size_t)b * KVS + k0 + i) * T_ENC + te0 + tx;
        g_keyT[o] = v;
        g_keyH[o] = __float2half(v);
    }
}

__global__ void convert_value(const float* __restrict__ value) {
    size_t i4 = ((size_t)blockIdx.x * blockDim.x + threadIdx.x) * 4;
    const size_t n = (size_t)B * T_ENC * KVS;
    if (i4 < n) {
        float4 v = *(const float4*)(value + i4);
        __half2* dst = (__half2*)(g_valH + i4);
        dst[0] = __floats2half2_rn(v.x, v.y);
        dst[1] = __floats2half2_rn(v.z, v.w);
    }
}

__global__ void build_table(const float* __restrict__ emb, const float* __restrict__ W_ih,
                            const float* __restrict__ b_ih, const float* __restrict__ b_hh) {
    __shared__ float e_s[EMBED];
    int v = blockIdx.x, g = threadIdx.x;          // 31 blocks x 512 threads
    if (v < VOCAB && g < EMBED) e_s[g] = emb[v * EMBED + g];
    __syncthreads();
    float acc = b_ih[g] + b_hh[g];
    if (v < VOCAB) {
        const float* w = W_ih + (size_t)g * XDIM;
        #pragma unroll 4
        for (int e = 0; e < EMBED; e++) acc += e_s[e] * w[e];
    }
    g_table[v * GATES + g] = acc;
}

__global__ void build_wrt(const float* __restrict__ W_ih, const float* __restrict__ W_hh) {
    int idx = blockIdx.x * blockDim.x + threadIdx.x;   // idx = j*512+g
    if (idx >= JROWS * GATES) return;
    int j = idx >> 9, g = idx & 511;
    float w = (j < KVS) ? W_ih[(size_t)g * XDIM + EMBED + j]
                        : W_hh[(size_t)g * KVS + (j - KVS)];
    g_WrH[idx] = __float2half(w);
}

// -------- main persistent decoder: 1 CTA per batch element, 512 threads --------
__global__ __launch_bounds__(NT, 1)
void decoder_kernel(const float* __restrict__ value, const int* __restrict__ y,
                    const float* __restrict__ emb, const float* __restrict__ b_cp,
                    float* __restrict__ out) {
    extern __shared__ float sm[];
    float* s_table = sm;                         // 15872
    float* s_emb   = s_table + TABLE_F;          // 7680
    float* s_hc    = s_emb + EMB_F;              // [0..127]=h, [128..255]=ctx
    float* s_c     = s_hc + 256;                 // 128
    float* s_attn  = s_c + 128;                  // 1024
    float* s_part  = s_attn + 1024;              // 2048
    float* s_red   = s_part + 2048;              // 72
    float* s_bcp   = s_red + 72;                 // 32

    const int b    = blockIdx.x;
    const int tid  = threadIdx.x;
    const int lane = tid & 31, wid = tid >> 5;   // 16 warps

    for (int i = tid; i < TABLE_F; i += NT) s_table[i] = g_table[i];
    for (int i = tid; i < EMB_F;   i += NT) s_emb[i]   = emb[i];
    if (tid < VOCAB) s_bcp[tid] = b_cp[tid];
    if (tid < KVS) {
        s_hc[tid] = 0.0f;
        s_c[tid]  = 0.0f;
        s_hc[KVS + tid] = value[(size_t)b * T_ENC * KVS + tid];   // ctx0 = value[b,0,:] (fp32)
    }

    const uint2*  V2 = (const uint2*)(g_valH + (size_t)b * T_ENC * KVS);
    const float4* K4 = (const float4*)(g_keyT + (size_t)b * KVS * T_ENC); // fp32 (b==0)
    const uint2*  K2 = (const uint2*)(g_keyH + (size_t)b * KVS * T_ENC);  // fp16 (b>0)
    const uint2*  WH = (const uint2*)g_WrH;                                // [j][g4]
    float* out_pred = out + (size_t)b * MAX_LEN * VOCAB;
    float* out_attn = out + (size_t)B * MAX_LEN * VOCAB;   // only b==0 writes

    const int g4  = tid & 127, jc  = tid >> 7;   // phase A: jc in 0..3, 64 j each
    const int te4 = tid & 255, kc  = tid >> 8;   // phase C: kc in 0..1, 64 k each
    const int k4  = tid & 31,  tec = tid >> 5;   // phase E: tec in 0..15, 64 te each
    const float* xptr = (jc < 2) ? (s_hc + KVS) : (s_hc - KVS);  // x[j]: ctx j<128, h j>=128

    // ---- register cache: even j-rows of my chunk (32 rows x 4 gates = 64 regs) ----
    uint2 wreg[32];
    #pragma unroll
    for (int r = 0; r < 32; r++)
        wreg[r] = WH[(jc * 64 + 2 * r) * 128 + g4];

    __syncthreads();

    for (int t = 0; t < MAX_LEN; t++) {
        // ---- Phase A: gate partials; even rows from regs, odd rows from L2 ----
        const int iv = (t == 0) ? VOCAB : y[b * MAX_LEN + t - 1];
        {
            float4 acc = make_float4(0.f, 0.f, 0.f, 0.f);
            const int j0 = jc * 64;
            #pragma unroll
            for (int r = 0; r < 32; r++) {
                const int j = j0 + 2 * r;
                {   // even row from register
                    const float x = xptr[j];
                    const uint2 raw = wreg[r];
                    const float2 f01 = __half22float2(*(const __half2*)&raw.x);
                    const float2 f23 = __half22float2(*(const __half2*)&raw.y);
                    acc.x += f01.x * x; acc.y += f01.y * x; acc.z += f23.x * x; acc.w += f23.y * x;
                }
                {   // odd row from L2
                    const float x = xptr[j + 1];
                    const uint2 raw = WH[(j + 1) * 128 + g4];
                    const float2 f01 = __half22float2(*(const __half2*)&raw.x);
                    const float2 f23 = __half22float2(*(const __half2*)&raw.y);
                    acc.x += f01.x * x; acc.y += f01.y * x; acc.z += f23.x * x; acc.w += f23.y * x;
                }
            }
            ((float4*)s_part)[jc * 128 + g4] = acc;   // 4 chunks x 512 floats
        }
        __syncthreads();                                             // sync 1

        // ---- fused gate-reduce + LSTM: thread tid<128 owns gates tid+q*128 ----
        if (tid < KVS) {
            float gv[4];
            #pragma unroll
            for (int q = 0; q < 4; q++) {
                const int g = tid + q * KVS;
                float v = s_table[iv * GATES + g];
                #pragma unroll
                for (int c = 0; c < 4; c++) v += s_part[c * GATES + g];
                gv[q] = v;
            }
            const float c_new = sigm(gv[1]) * s_c[tid] + sigm(gv[0]) * tanhf(gv[2]);
            const float h_new = sigm(gv[3]) * tanhf(c_new);
            s_c[tid]  = c_new;
            s_hc[tid] = h_new;
        }
        __syncthreads();                                             // sync 2

        // ---- Phase C: energy[te] = key[b,:,te] . h  (2 k-chunks of 64) ----
        if (b == 0) {   // exact fp32 key for the directly-output attention
            float4 e = make_float4(0.f, 0.f, 0.f, 0.f);
            const int kk0 = kc * 64;
            #pragma unroll 8
            for (int kk = 0; kk < 64; kk++) {
                const float hk = s_hc[kk0 + kk];
                const float4 kv = K4[(kk0 + kk) * (T_ENC / 4) + te4];
                e.x += kv.x * hk; e.y += kv.y * hk; e.z += kv.z * hk; e.w += kv.w * hk;
            }
            ((float4*)s_part)[kc * 256 + te4] = e;
        } else {
            float4 e = make_float4(0.f, 0.f, 0.f, 0.f);
            const int kk0 = kc * 64;
            #pragma unroll 8
            for (int kk = 0; kk < 64; kk++) {
                const float hk = s_hc[kk0 + kk];
                const uint2 raw = K2[(kk0 + kk) * (T_ENC / 4) + te4];
                const float2 f01 = __half22float2(*(const __half2*)&raw.x);
                const float2 f23 = __half22float2(*(const __half2*)&raw.y);
                e.x += f01.x * hk; e.y += f01.y * hk; e.z += f23.x * hk; e.w += f23.y * hk;
            }
            ((float4*)s_part)[kc * 256 + te4] = e;
        }
        __syncthreads();                                             // sync 3

        // ---- Phase D: softmax over 1024, 2 te per thread ----
        const float ev0 = s_part[tid]       + s_part[1024 + tid];
        const float ev1 = s_part[512 + tid] + s_part[1536 + tid];
        float m = fmaxf(ev0, ev1);
        #pragma unroll
        for (int o = 16; o; o >>= 1) m = fmaxf(m, __shfl_xor_sync(0xFFFFFFFFu, m, o));
        if (lane == 0) s_red[wid] = m;
        __syncthreads();                                             // sync 4
        {
            float mm = (lane < 16) ? s_red[lane] : -1e30f;
            #pragma unroll
            for (int o = 16; o; o >>= 1) mm = fmaxf(mm, __shfl_xor_sync(0xFFFFFFFFu, mm, o));
            m = mm;
        }
        const float ex0 = expf(ev0 - m);
        const float ex1 = expf(ev1 - m);
        float su = ex0 + ex1;
        #pragma unroll
        for (int o = 16; o; o >>= 1) su += __shfl_xor_sync(0xFFFFFFFFu, su, o);
        if (lane == 0) s_red[32 + wid] = su;
        __syncthreads();                                             // sync 5
        {
            float ss = (lane < 16) ? s_red[32 + lane] : 0.0f;
            #pragma unroll
            for (int o = 16; o; o >>= 1) ss += __shfl_xor_sync(0xFFFFFFFFu, ss, o);
            su = ss;
        }
        const float at0 = ex0 / su;
        const float at1 = ex1 / su;
        s_attn[tid] = at0;
        s_attn[512 + tid] = at1;
        if (b == 0) {
            out_attn[(size_t)t * T_ENC + tid] = at0;
            out_attn[(size_t)t * T_ENC + 512 + tid] = at1;
        }
        __syncthreads();                                             // sync 6

        // ---- Phase E: ctx[k] = sum_te attn[te] * value[b,te,k]  (16 te-chunks of 64) ----
        {
            float4 acc = make_float4(0.f, 0.f, 0.f, 0.f);
            const int t0 = tec * 64;
            #pragma unroll 8
            for (int te = 0; te < 64; te++) {
                const float a = s_attn[t0 + te];
                const uint2 raw = V2[(t0 + te) * (KVS / 4) + k4];
                const float2 f01 = __half22float2(*(const __half2*)&raw.x);
                const float2 f23 = __half22float2(*(const __half2*)&raw.y);
                acc.x += f01.x * a; acc.y += f01.y * a; acc.z += f23.x * a; acc.w += f23.y * a;
            }
            ((float4*)s_part)[tec * (KVS / 4) + k4] = acc;   // 16 x 128 floats
        }
        __syncthreads();                                             // sync 7
        if (tid < KVS) {
            float cv = 0.f;
            #pragma unroll
            for (int c = 0; c < 16; c++) cv += s_part[c * KVS + tid];
            s_hc[KVS + tid] = cv;
        }
        __syncthreads();                                             // sync 8

        // ---- Phase F: predictions, 2 vocab per warp (16 warps) ----
        {
            const int v0 = wid, v1 = wid + 16;
            float a0 = 0.f, a1 = 0.f;
            #pragma unroll
            for (int e = lane; e < EMBED; e += 32) {
                const float h = s_hc[e];
                a0 += h * s_emb[v0 * EMBED + e];
                if (v1 < VOCAB) a1 += h * s_emb[v1 * EMBED + e];
            }
            #pragma unroll
            for (int o = 16; o; o >>= 1) {
                a0 += __shfl_xor_sync(0xFFFFFFFFu, a0, o);
                a1 += __shfl_xor_sync(0xFFFFFFFFu, a1, o);
            }
            if (lane == 0) {
                out_pred[t * VOCAB + v0] = a0 + s_bcp[v0];
                if (v1 < VOCAB) out_pred[t * VOCAB + v1] = a1 + s_bcp[v1];
            }
        }
        // next iteration's sync 1 rejoins all warps; Phase F reads only s_hc/s_emb
        // which nothing writes before the fused LSTM (after sync 2) of the next step.
    }
}

extern "C" void kernel_launch(void* const* d_in, const int* in_sizes, int n_in,
                              void* d_out, int out_size) {
    const float* key   = (const float*)d_in[0];
    const float* value = (const float*)d_in[1];
    // d_in[2] = encoder_len : unused by the reference
    const int*   y     = (const int*)d_in[3];
    const float* emb   = (const float*)d_in[4];
    const float* W_ih  = (const float*)d_in[5];
    const float* W_hh  = (const float*)d_in[6];
    const float* b_ih  = (const float*)d_in[7];
    const float* b_hh  = (const float*)d_in[8];
    const float* b_cp  = (const float*)d_in[9];
    float* out = (float*)d_out;

    cudaFuncSetAttribute(decoder_kernel, cudaFuncAttributeMaxDynamicSharedMemorySize, SMEM_BYTES);

    dim3 tb(32, 8);
    dim3 tg(T_ENC / 32, KVS / 32, B);
    transpose_key<<<tg, tb>>>(key);
    {
        const size_t n4 = ((size_t)B * T_ENC * KVS) / 4;
        convert_value<<<(int)((n4 + 255) / 256), 256>>>(value);
    }
    build_table<<<VOCAB + 1, GATES>>>(emb, W_ih, b_ih, b_hh);
    build_wrt<<<(JROWS * GATES + 255) / 256, 256>>>(W_ih, W_hh);
    decoder_kernel<<<B, NT, SMEM_BYTES>>>(value, y, emb, b_cp, out);
}

// round 16
// speedup vs baseline: 1.2674x; 1.2674x over previous
#include <cuda_runtime.h>
#include <cuda_fp16.h>
#include <stdint.h>
#include <math.h>

#define B        128
#define T_ENC    1024
#define KVS      128
#define EMBED    256
#define VOCAB    30
#define MAX_LEN  250
#define GATES    512     // 4*KVS
#define XDIM     384     // EMBED+KVS
#define JROWS    (2*KVS) // 256 rows of recurrent weight matrix [j][g]

// -------- persistent device scratch (no allocs allowed) --------
__device__ float  g_keyT[(size_t)B * KVS * T_ENC];     // [b][k][te] fp32 (b==0: exact attn)
__device__ __half g_keyH[(size_t)B * KVS * T_ENC];     // [b][k][te] fp16 (all other b)
__device__ __half g_valH[(size_t)B * T_ENC * KVS];     // [b][te][k] fp16
__device__ float  g_table[(VOCAB + 1) * GATES];        // [v][g], row VOCAB = bias-only
__device__ __half g_WrH[JROWS * GATES];                // [j][g] fp16; j<128: ctx w., j>=128: h w.

// -------- shared memory layout (floats) — table REMOVED, L1 carveout ~175 KB --------
#define EMB_F    (VOCAB * EMBED)         // 7680
#define SMEM_F   (EMB_F + 256 + 128 + 1024 + 4096 + 72 + 32)
#define SMEM_BYTES (SMEM_F * 4)          // ~53 KB

__device__ __forceinline__ float sigm(float x) { return 1.0f / (1.0f + expf(-x)); }

// -------- preprocessing kernels --------
__global__ void transpose_key(const float* __restrict__ key) {
    __shared__ float tile[32][33];
    int b   = blockIdx.z;
    int te0 = blockIdx.x * 32;
    int k0  = blockIdx.y * 32;
    int tx = threadIdx.x, ty = threadIdx.y;       // (32, 8)
    #pragma unroll
    for (int i = ty; i < 32; i += 8)
        tile[i][tx] = key[((size_t)b * T_ENC + te0 + i) * KVS + k0 + tx];
    __syncthreads();
    #pragma unroll
    for (int i = ty; i < 32; i += 8) {
        const float v = tile[tx][i];
        const size_t o = ((size_t)b * KVS + k0 + i) * T_ENC + te0 + tx;
        g_keyT[o] = v;
        g_keyH[o] = __float2half(v);
    }
}

__global__ void convert_value(const float* __restrict__ value) {
    size_t i4 = ((size_t)blockIdx.x * blockDim.x + threadIdx.x) * 4;
    const size_t n = (size_t)B * T_ENC * KVS;
    if (i4 < n) {
        float4 v = *(const float4*)(value + i4);
        __half2* dst = (__half2*)(g_valH + i4);
        dst[0] = __floats2half2_rn(v.x, v.y);
        dst[1] = __floats2half2_rn(v.z, v.w);
    }
}

__global__ void build_table(const float* __restrict__ emb, const float* __restrict__ W_ih,
                            const float* __restrict__ b_ih, const float* __restrict__ b_hh) {
    __shared__ float e_s[EMBED];
    int v = blockIdx.x, g = threadIdx.x;          // 31 blocks x 512 threads
    if (v < VOCAB && g < EMBED) e_s[g] = emb[v * EMBED + g];
    __syncthreads();
    float acc = b_ih[g] + b_hh[g];
    if (v < VOCAB) {
        const float* w = W_ih + (size_t)g * XDIM;
        #pragma unroll 4
        for (int e = 0; e < EMBED; e++) acc += e_s[e] * w[e];
    }
    g_table[v * GATES + g] = acc;
}

__global__ void build_wrt(const float* __restrict__ W_ih, const float* __restrict__ W_hh) {
    int idx = blockIdx.x * blockDim.x + threadIdx.x;   // idx = j*512+g
    if (idx >= JROWS * GATES) return;
    int j = idx >> 9, g = idx & 511;
    float w = (j < KVS) ? W_ih[(size_t)g * XDIM + EMBED + j]
                        : W_hh[(size_t)g * KVS + (j - KVS)];
    g_WrH[idx] = __float2half(w);
}

// -------- main persistent decoder: 1 CTA per batch element --------
__global__ __launch_bounds__(1024, 1)
void decoder_kernel(const float* __restrict__ value, const int* __restrict__ y,
                    const float* __restrict__ emb, const float* __restrict__ b_cp,
                    float* __restrict__ out) {
    extern __shared__ float sm[];
    float* s_emb   = sm;                         // 7680
    float* s_hc    = s_emb + EMB_F;              // [0..127]=h, [128..255]=ctx
    float* s_c     = s_hc + 256;                 // 128
    float* s_attn  = s_c + 128;                  // 1024
    float* s_part  = s_attn + 1024;              // 4096
    float* s_red   = s_part + 4096;              // 72
    float* s_bcp   = s_red + 72;                 // 32

    const int b    = blockIdx.x;
    const int tid  = threadIdx.x;
    const int lane = tid & 31, wid = tid >> 5;

    for (int i = tid; i < EMB_F; i += 1024) s_emb[i] = emb[i];
    if (tid < VOCAB) s_bcp[tid] = b_cp[tid];
    if (tid < KVS) {
        s_hc[tid] = 0.0f;
        s_c[tid]  = 0.0f;
        s_hc[KVS + tid] = value[(size_t)b * T_ENC * KVS + tid];   // ctx0 = value[b,0,:] (fp32)
    }
    __syncthreads();

    const uint2*  V2 = (const uint2*)(g_valH + (size_t)b * T_ENC * KVS);
    const float4* K4 = (const float4*)(g_keyT + (size_t)b * KVS * T_ENC); // fp32 (b==0)
    const uint2*  K2 = (const uint2*)(g_keyH + (size_t)b * KVS * T_ENC);  // fp16 (b>0)
    const uint2*  WH = (const uint2*)g_WrH;                                // [j][g4], 4 halves
    float* out_pred = out + (size_t)b * MAX_LEN * VOCAB;
    float* out_attn = out + (size_t)B * MAX_LEN * VOCAB;   // only b==0 writes

    const int g4  = tid & 127, jc  = tid >> 7;   // gate GEMV decomposition (8 chunks of 32 j)
    const int te4 = tid & 255, kc  = tid >> 8;   // energy decomposition (4 k-chunks)
    const int k4  = tid & 31,  tec = tid >> 5;   // ctx decomposition
    const float* xptr = (jc < 4) ? (s_hc + KVS) : (s_hc - KVS);  // xptr[j]: ctx j<128, h j>=128

    for (int t = 0; t < MAX_LEN; t++) {
        // ---- Phase A: gate partials = [Wctx|Whh] @ [ctx;h] ----
        // W uses DEFAULT caching -> lives in the (now ~175 KB) L1 carveout across steps.
        const int iv = (t == 0) ? VOCAB : y[b * MAX_LEN + t - 1];
        {
            float4 acc = make_float4(0.f, 0.f, 0.f, 0.f);
            const int j0 = jc * 32;
            #pragma unroll 8
            for (int jj = 0; jj < 32; jj++) {
                const int j = j0 + jj;
                const float x = xptr[j];
                const uint2 raw = WH[j * (GATES / 4) + g4];
                const float2 f01 = __half22float2(*(const __half2*)&raw.x);
                const float2 f23 = __half22float2(*(const __half2*)&raw.y);
                acc.x += f01.x * x; acc.y += f01.y * x; acc.z += f23.x * x; acc.w += f23.y * x;
            }
            ((float4*)s_part)[jc * (GATES / 4) + g4] = acc;
        }
        __syncthreads();                                             // sync 1

        // ---- fused gate-reduce + LSTM: thread tid<128 owns gates tid+q*128 ----
        if (tid < KVS) {
            float gv[4];
            #pragma unroll
            for (int q = 0; q < 4; q++) {
                const int g = tid + q * KVS;
                float v = g_table[iv * GATES + g];   // 2 KB/step, default caching
                #pragma unroll
                for (int c = 0; c < 8; c++) v += s_part[c * GATES + g];
                gv[q] = v;
            }
            const float c_new = sigm(gv[1]) * s_c[tid] + sigm(gv[0]) * tanhf(gv[2]);
            const float h_new = sigm(gv[3]) * tanhf(c_new);
            s_c[tid]  = c_new;
            s_hc[tid] = h_new;
        }
        __syncthreads();                                             // sync 2

        // ---- Phase C: energy[te] = key[b,:,te] . h  (streams bypass L1 via .cg) ----
        if (b == 0) {   // exact fp32 key for the directly-output attention
            float4 e = make_float4(0.f, 0.f, 0.f, 0.f);
            const int kk0 = kc * 32;
            #pragma unroll 8
            for (int kk = 0; kk < 32; kk++) {
                const float hk = s_hc[kk0 + kk];
                const float4 kv = __ldcg(&K4[(kk0 + kk) * (T_ENC / 4) + te4]);
                e.x += kv.x * hk; e.y += kv.y * hk; e.z += kv.z * hk; e.w += kv.w * hk;
            }
            ((float4*)s_part)[kc * (T_ENC / 4) + te4] = e;
        } else {
            float4 e = make_float4(0.f, 0.f, 0.f, 0.f);
            const int kk0 = kc * 32;
            #pragma unroll 8
            for (int kk = 0; kk < 32; kk++) {
                const float hk = s_hc[kk0 + kk];
                const uint2 raw = __ldcg(&K2[(kk0 + kk) * (T_ENC / 4) + te4]);
                const float2 f01 = __half22float2(*(const __half2*)&raw.x);
                const float2 f23 = __half22float2(*(const __half2*)&raw.y);
                e.x += f01.x * hk; e.y += f01.y * hk; e.z += f23.x * hk; e.w += f23.y * hk;
            }
            ((float4*)s_part)[kc * (T_ENC / 4) + te4] = e;
        }
        __syncthreads();                                             // sync 3

        // ---- Phase D: lean softmax over 1024 (te = tid) ----
        const float ev = s_part[tid] + s_part[T_ENC + tid]
                       + s_part[2 * T_ENC + tid] + s_part[3 * T_ENC + tid];
        float m = ev;
        #pragma unroll
        for (int o = 16; o; o >>= 1) m = fmaxf(m, __shfl_xor_sync(0xFFFFFFFFu, m, o));
        if (lane == 0) s_red[wid] = m;
        __syncthreads();                                             // sync 4
        {
            float mm = s_red[lane];
            #pragma unroll
            for (int o = 16; o; o >>= 1) mm = fmaxf(mm, __shfl_xor_sync(0xFFFFFFFFu, mm, o));
            m = mm;
        }
        const float ex = expf(ev - m);
        float su = ex;
        #pragma unroll
        for (int o = 16; o; o >>= 1) su += __shfl_xor_sync(0xFFFFFFFFu, su, o);
        if (lane == 0) s_red[32 + wid] = su;
        __syncthreads();                                             // sync 5
        {
            float ss = s_red[32 + lane];
            #pragma unroll
            for (int o = 16; o; o >>= 1) ss += __shfl_xor_sync(0xFFFFFFFFu, ss, o);
            su = ss;
        }
        const float attnv = ex / su;
        s_attn[tid] = attnv;
        if (b == 0) out_attn[(size_t)t * T_ENC + tid] = attnv;
        __syncthreads();                                             // sync 6

        // ---- Phase E: ctx[k] = sum_te attn[te] * value[b,te,k]  (.cg stream) ----
        {
            float4 acc = make_float4(0.f, 0.f, 0.f, 0.f);
            const int t0 = tec * 32;
            #pragma unroll 8
            for (int te = 0; te < 32; te++) {
                const float a = s_attn[t0 + te];
                const uint2 raw = __ldcg(&V2[(t0 + te) * (KVS / 4) + k4]);
                const float2 f01 = __half22float2(*(const __half2*)&raw.x);
                const float2 f23 = __half22float2(*(const __half2*)&raw.y);
                acc.x += f01.x * a; acc.y += f01.y * a; acc.z += f23.x * a; acc.w += f23.y * a;
            }
            ((float4*)s_part)[tec * (KVS / 4) + k4] = acc;
        }
        __syncthreads();                                             // sync 7
        if (tid < KVS) {
            float cv = 0.f;
            #pragma unroll
            for (int c = 0; c < 32; c++) cv += s_part[c * KVS + tid];
            s_hc[KVS + tid] = cv;
        }
        __syncthreads();                                             // sync 8

        // ---- Phase F: pred[v] = [h;ctx] . emb[v] + b_cp[v] (warp per vocab) ----
        if (wid < VOCAB) {
            const int v = wid;
            float acc = 0.f;
            #pragma unroll
            for (int e = lane; e < EMBED; e += 32) acc += s_hc[e] * s_emb[v * EMBED + e];
            #pragma unroll
            for (int o = 16; o; o >>= 1) acc += __shfl_xor_sync(0xFFFFFFFFu, acc, o);
            if (lane == 0) out_pred[t * VOCAB + v] = acc + s_bcp[v];
        }
        // next iteration's sync 1 rejoins all warps; Phase F reads only s_hc/s_emb
        // which nothing writes before the fused LSTM (after sync 2) of the next step.
    }
}

extern "C" void kernel_launch(void* const* d_in, const int* in_sizes, int n_in,
                              void* d_out, int out_size) {
    const float* key   = (const float*)d_in[0];
    const float* value = (const float*)d_in[1];
    // d_in[2] = encoder_len : unused by the reference
    const int*   y     = (const int*)d_in[3];
    const float* emb   = (const float*)d_in[4];
    const float* W_ih  = (const float*)d_in[5];
    const float* W_hh  = (const float*)d_in[6];
    const float* b_ih  = (const float*)d_in[7];
    const float* b_hh  = (const float*)d_in[8];
    const float* b_cp  = (const float*)d_in[9];
    float* out = (float*)d_out;

    cudaFuncSetAttribute(decoder_kernel, cudaFuncAttributeMaxDynamicSharedMemorySize, SMEM_BYTES);

    dim3 tb(32, 8);
    dim3 tg(T_ENC / 32, KVS / 32, B);
    transpose_key<<<tg, tb>>>(key);
    {
        const size_t n4 = ((size_t)B * T_ENC * KVS) / 4;
        convert_value<<<(int)((n4 + 255) / 256), 256>>>(value);
    }
    build_table<<<VOCAB + 1, GATES>>>(emb, W_ih, b_ih, b_hh);
    build_wrt<<<(JROWS * GATES + 255) / 256, 256>>>(W_ih, W_hh);
    decoder_kernel<<<B, 1024, SMEM_BYTES>>>(value, y, emb, b_cp, out);
}

// round 17
// speedup vs baseline: 1.3448x; 1.0611x over previous
#include <cuda_runtime.h>
#include <cuda_fp16.h>
#include <stdint.h>
#include <math.h>

#define B        128
#define T_ENC    1024
#define KVS      128
#define EMBED    256
#define VOCAB    30
#define MAX_LEN  250
#define GATES    512     // 4*KVS
#define XDIM     384     // EMBED+KVS
#define JROWS    (2*KVS) // 256 rows of recurrent weight matrix [j][g]

// -------- persistent device scratch (no allocs allowed) --------
__device__ float  g_keyT[(size_t)B * KVS * T_ENC];     // [b][k][te] fp32 (b==0: exact attn)
__device__ __half g_keyH[(size_t)B * KVS * T_ENC];     // [b][k][te] fp16 (all other b)
__device__ __half g_valH[(size_t)B * T_ENC * KVS];     // [b][te][k] fp16
__device__ float  g_table[(VOCAB + 1) * GATES];        // [v][g], row VOCAB = bias-only
__device__ __half g_WrH[JROWS * GATES];                // [j][g] fp16; j<128: ctx w., j>=128: h w.

// -------- shared memory layout (floats) — identical to R11 --------
#define TABLE_F  ((VOCAB + 1) * GATES)   // 15872
#define EMB_F    (VOCAB * EMBED)         // 7680
#define SMEM_F   (TABLE_F + EMB_F + 256 + 128 + 1024 + 4096 + 72 + 32)
#define SMEM_BYTES (SMEM_F * 4)          // ~116.6 KB

__device__ __forceinline__ float sigm(float x) { return 1.0f / (1.0f + expf(-x)); }

// -------- preprocessing kernels --------
__global__ void transpose_key(const float* __restrict__ key) {
    __shared__ float tile[32][33];
    int b   = blockIdx.z;
    int te0 = blockIdx.x * 32;
    int k0  = blockIdx.y * 32;
    int tx = threadIdx.x, ty = threadIdx.y;       // (32, 8)
    #pragma unroll
    for (int i = ty; i < 32; i += 8)
        tile[i][tx] = key[((size_t)b * T_ENC + te0 + i) * KVS + k0 + tx];
    __syncthreads();
    #pragma unroll
    for (int i = ty; i < 32; i += 8) {
        const float v = tile[tx][i];
        const size_t o = ((size_t)b * KVS + k0 + i) * T_ENC + te0 + tx;
        g_keyT[o] = v;
        g_keyH[o] = __float2half(v);
    }
}

__global__ void convert_value(const float* __restrict__ value) {
    size_t i4 = ((size_t)blockIdx.x * blockDim.x + threadIdx.x) * 4;
    const size_t n = (size_t)B * T_ENC * KVS;
    if (i4 < n) {
        float4 v = *(const float4*)(value + i4);
        __half2* dst = (__half2*)(g_valH + i4);
        dst[0] = __floats2half2_rn(v.x, v.y);
        dst[1] = __floats2half2_rn(v.z, v.w);
    }
}

__global__ void build_table(const float* __restrict__ emb, const float* __restrict__ W_ih,
                            const float* __restrict__ b_ih, const float* __restrict__ b_hh) {
    __shared__ float e_s[EMBED];
    int v = blockIdx.x, g = threadIdx.x;          // 31 blocks x 512 threads
    if (v < VOCAB && g < EMBED) e_s[g] = emb[v * EMBED + g];
    __syncthreads();
    float acc = b_ih[g] + b_hh[g];
    if (v < VOCAB) {
        const float* w = W_ih + (size_t)g * XDIM;
        #pragma unroll 4
        for (int e = 0; e < EMBED; e++) acc += e_s[e] * w[e];
    }
    g_table[v * GATES + g] = acc;
}

__global__ void build_wrt(const float* __restrict__ W_ih, const float* __restrict__ W_hh) {
    int idx = blockIdx.x * blockDim.x + threadIdx.x;   // idx = j*512+g
    if (idx >= JROWS * GATES) return;
    int j = idx >> 9, g = idx & 511;
    float w = (j < KVS) ? W_ih[(size_t)g * XDIM + EMBED + j]
                        : W_hh[(size_t)g * KVS + (j - KVS)];
    g_WrH[idx] = __float2half(w);
}

// -------- main persistent decoder: 1 CTA per batch element --------
__global__ __launch_bounds__(1024, 1)
void decoder_kernel(const float* __restrict__ value, const int* __restrict__ y,
                    const float* __restrict__ emb, const float* __restrict__ b_cp,
                    float* __restrict__ out) {
    extern __shared__ float sm[];
    float* s_table = sm;                         // 15872
    float* s_emb   = s_table + TABLE_F;          // 7680
    float* s_hc    = s_emb + EMB_F;              // [0..127]=h, [128..255]=ctx
    float* s_c     = s_hc + 256;                 // 128
    float* s_attn  = s_c + 128;                  // 1024
    float* s_part  = s_attn + 1024;              // 4096
    float* s_red   = s_part + 4096;              // 72
    float* s_bcp   = s_red + 72;                 // 32

    const int b    = blockIdx.x;
    const int tid  = threadIdx.x;
    const int lane = tid & 31, wid = tid >> 5;

    for (int i = tid; i < TABLE_F; i += 1024) s_table[i] = g_table[i];
    for (int i = tid; i < EMB_F;   i += 1024) s_emb[i]   = emb[i];
    if (tid < VOCAB) s_bcp[tid] = b_cp[tid];
    if (tid < KVS) {
        s_hc[tid] = 0.0f;
        s_c[tid]  = 0.0f;
        s_hc[KVS + tid] = value[(size_t)b * T_ENC * KVS + tid];   // ctx0 = value[b,0,:] (fp32)
    }
    __syncthreads();

    const uint2*  V2 = (const uint2*)(g_valH + (size_t)b * T_ENC * KVS);
    const float4* K4 = (const float4*)(g_keyT + (size_t)b * KVS * T_ENC); // fp32 (b==0)
    const uint2*  K2 = (const uint2*)(g_keyH + (size_t)b * KVS * T_ENC);  // fp16 (b>0)
    const uint2*  WH = (const uint2*)g_WrH;                                // [j][g4], 4 halves
    float* out_pred = out + (size_t)b * MAX_LEN * VOCAB;
    float* out_attn = out + (size_t)B * MAX_LEN * VOCAB;   // only b==0 writes

    const int g4  = tid & 127, jc  = tid >> 7;   // gate GEMV decomposition (8 chunks of 32 j)
    const int te4 = tid & 255, kc  = tid >> 8;   // energy decomposition (4 k-chunks)
    const int k4  = tid & 31,  tec = tid >> 5;   // ctx decomposition
    const float* xptr = (jc < 4) ? (s_hc + KVS) : (s_hc - KVS);  // xptr[j]: ctx j<128, h j>=128

    for (int t = 0; t < MAX_LEN; t++) {
        // ---- Phase A: gate partials = [Wctx|Whh] @ [ctx;h]  (W fp16 from L2) ----
        const int iv = (t == 0) ? VOCAB : y[b * MAX_LEN + t - 1];
        {
            float4 acc = make_float4(0.f, 0.f, 0.f, 0.f);
            const int j0 = jc * 32;
            #pragma unroll 8
            for (int jj = 0; jj < 32; jj++) {
                const int j = j0 + jj;
                const float x = xptr[j];
                const uint2 raw = WH[j * (GATES / 4) + g4];
                const float2 f01 = __half22float2(*(const __half2*)&raw.x);
                const float2 f23 = __half22float2(*(const __half2*)&raw.y);
                acc.x += f01.x * x; acc.y += f01.y * x; acc.z += f23.x * x; acc.w += f23.y * x;
            }
            ((float4*)s_part)[jc * (GATES / 4) + g4] = acc;
        }
        __syncthreads();                                             // sync 1

        // ---- fused gate-reduce + LSTM: thread tid<128 owns gates tid+q*128 ----
        if (tid < KVS) {
            float gv[4];
            #pragma unroll
            for (int q = 0; q < 4; q++) {
                const int g = tid + q * KVS;
                float v = s_table[iv * GATES + g];
                #pragma unroll
                for (int c = 0; c < 8; c++) v += s_part[c * GATES + g];
                gv[q] = v;
            }
            const float c_new = sigm(gv[1]) * s_c[tid] + sigm(gv[0]) * tanhf(gv[2]);
            const float h_new = sigm(gv[3]) * tanhf(c_new);
            s_c[tid]  = c_new;
            s_hc[tid] = h_new;
        }
        __syncthreads();                                             // sync 2

        // ---- Phase C: energy[te] = key[b,:,te] . h ----
        if (b == 0) {   // exact fp32 key for the directly-output attention
            float4 e = make_float4(0.f, 0.f, 0.f, 0.f);
            const int kk0 = kc * 32;
            #pragma unroll 8
            for (int kk = 0; kk < 32; kk++) {
                const float hk = s_hc[kk0 + kk];
                const float4 kv = K4[(kk0 + kk) * (T_ENC / 4) + te4];
                e.x += kv.x * hk; e.y += kv.y * hk; e.z += kv.z * hk; e.w += kv.w * hk;
            }
            ((float4*)s_part)[kc * (T_ENC / 4) + te4] = e;
        } else {
            float4 e = make_float4(0.f, 0.f, 0.f, 0.f);
            const int kk0 = kc * 32;
            #pragma unroll 8
            for (int kk = 0; kk < 32; kk++) {
                const float hk = s_hc[kk0 + kk];
                const uint2 raw = K2[(kk0 + kk) * (T_ENC / 4) + te4];
                const float2 f01 = __half22float2(*(const __half2*)&raw.x);
                const float2 f23 = __half22float2(*(const __half2*)&raw.y);
                e.x += f01.x * hk; e.y += f01.y * hk; e.z += f23.x * hk; e.w += f23.y * hk;
            }
            ((float4*)s_part)[kc * (T_ENC / 4) + te4] = e;
        }
        __syncthreads();                                             // sync 3

        // ---- Phase D: ONLINE softmax over 1024 (te = tid), single publish sync ----
        const float ev = s_part[tid] + s_part[T_ENC + tid]
                       + s_part[2 * T_ENC + tid] + s_part[3 * T_ENC + tid];
        float mw = ev;
        #pragma unroll
        for (int o = 16; o; o >>= 1) mw = fmaxf(mw, __shfl_xor_sync(0xFFFFFFFFu, mw, o));
        const float el = __expf(ev - mw);      // warp-local exp
        float sw = el;
        #pragma unroll
        for (int o = 16; o; o >>= 1) sw += __shfl_xor_sync(0xFFFFFFFFu, sw, o);
        if (lane == 0) { s_red[wid] = mw; s_red[32 + wid] = sw; }
        __syncthreads();                                             // sync 4
        float M, S;
        {
            const float ml_in = s_red[lane];
            float ml = ml_in;
            #pragma unroll
            for (int o = 16; o; o >>= 1) ml = fmaxf(ml, __shfl_xor_sync(0xFFFFFFFFu, ml, o));
            M = ml;
            float sl = s_red[32 + lane] * __expf(ml_in - M);
            #pragma unroll
            for (int o = 16; o; o >>= 1) sl += __shfl_xor_sync(0xFFFFFFFFu, sl, o);
            S = sl;
        }
        const float attnv = el * (__expf(mw - M) / S);
        s_attn[tid] = attnv;
        if (b == 0) out_attn[(size_t)t * T_ENC + tid] = attnv;
        __syncthreads();                                             // sync 5

        // ---- Phase E: ctx[k] = sum_te attn[te] * value[b,te,k]  (value fp16) ----
        {
            float4 acc = make_float4(0.f, 0.f, 0.f, 0.f);
            const int t0 = tec * 32;
            #pragma unroll 8
            for (int te = 0; te < 32; te++) {
                const float a = s_attn[t0 + te];
                const uint2 raw = V2[(t0 + te) * (KVS / 4) + k4];
                const float2 f01 = __half22float2(*(const __half2*)&raw.x);
                const float2 f23 = __half22float2(*(const __half2*)&raw.y);
                acc.x += f01.x * a; acc.y += f01.y * a; acc.z += f23.x * a; acc.w += f23.y * a;
            }
            ((float4*)s_part)[tec * (KVS / 4) + k4] = acc;
        }
        __syncthreads();                                             // sync 6
        if (tid < KVS) {
            float cv = 0.f;
            #pragma unroll
            for (int c = 0; c < 32; c++) cv += s_part[c * KVS + tid];
            s_hc[KVS + tid] = cv;
        }
        __syncthreads();                                             // sync 7

        // ---- Phase F: pred[v] = [h;ctx] . emb[v] + b_cp[v] (warp per vocab) ----
        if (wid < VOCAB) {
            const int v = wid;
            float acc = 0.f;
            #pragma unroll
            for (int e = lane; e < EMBED; e += 32) acc += s_hc[e] * s_emb[v * EMBED + e];
            #pragma unroll
            for (int o = 16; o; o >>= 1) acc += __shfl_xor_sync(0xFFFFFFFFu, acc, o);
            if (lane == 0) out_pred[t * VOCAB + v] = acc + s_bcp[v];
        }
        // next iteration's sync 1 rejoins all warps; Phase F reads only s_hc/s_emb
        // which nothing writes before the fused LSTM (after sync 2) of the next step.
    }
}

extern "C" void kernel_launch(void* const* d_in, const int* in_sizes, int n_in,
                              void* d_out, int out_size) {
    const float* key   = (const float*)d_in[0];
    const float* value = (const float*)d_in[1];
    // d_in[2] = encoder_len : unused by the reference
    const int*   y     = (const int*)d_in[3];
    const float* emb   = (const float*)d_in[4];
    const float* W_ih  = (const float*)d_in[5];
    const float* W_hh  = (const float*)d_in[6];
    const float* b_ih  = (const float*)d_in[7];
    const float* b_hh  = (const float*)d_in[8];
    const float* b_cp  = (const float*)d_in[9];
    float* out = (float*)d_out;

    cudaFuncSetAttribute(decoder_kernel, cudaFuncAttributeMaxDynamicSharedMemorySize, SMEM_BYTES);

    dim3 tb(32, 8);
    dim3 tg(T_ENC / 32, KVS / 32, B);
    transpose_key<<<tg, tb>>>(key);
    {
        const size_t n4 = ((size_t)B * T_ENC * KVS) / 4;
        convert_value<<<(int)((n4 + 255) / 256), 256>>>(value);
    }
    build_table<<<VOCAB + 1, GATES>>>(emb, W_ih, b_ih, b_hh);
    build_wrt<<<(JROWS * GATES + 255) / 256, 256>>>(W_ih, W_hh);
    decoder_kernel<<<B, 1024, SMEM_BYTES>>>(value, y, emb, b_cp, out);
}